// round 8
// baseline (speedup 1.0000x reference)
#include <cuda_runtime.h>
#include <cuda_bf16.h>
#include <cstdint>

#define NB   64
#define CC   64
#define TT   256
#define VV   25

typedef unsigned long long ull;

// ---------------- scratch (static device memory) ----------------
__device__ __align__(16) __nv_bfloat16 g_W9b[9 * 128 * 64];  // [tap][ch][cin]
__device__ __align__(16) __nv_bfloat16 g_W1b[160 * 64];      // [ch][cin]
__device__ float g_b9[128];
__device__ float g_b1[160];
__device__ float g_Acomb[625];
__device__ float g_Gram[64 * 9 * 625];
__device__ float g_A1[64 * 3 * 625];
__device__ __align__(16) float g_AfH[12288];  // tf32-hi A-fragments [4 strip][24 kt][32 lane][4]
__device__ __align__(16) float g_AfL[12288];  // tf32-lo
__device__ float g_bd2[64];

// branch tables
__constant__ int c_i9[8]  = {0,0,1,1,1,1,2,2};
__constant__ int c_s9[8]  = {0,1,0,1,2,3,0,1};
__constant__ int c_i1[10] = {0,0,0,0,1,1,2,2,2,2};
__constant__ int c_s1[10] = {0,1,2,3,0,1,0,1,2,3};
__constant__ int c_gi9[4] = {0,1,1,2};
__constant__ int c_gj9[4] = {1,1,2,1};
__constant__ int c_gi1[5] = {0,0,1,2,2};
__constant__ int c_gj1[5] = {0,2,0,0,2};

// ---------------- f32x2 helpers ----------------
__device__ __forceinline__ ull pack2(float lo, float hi) {
    ull r; asm("mov.b64 %0, {%1,%2};" : "=l"(r) : "f"(lo), "f"(hi)); return r;
}
__device__ __forceinline__ void fma2(ull& d, ull a, ull b) {
    asm("fma.rn.f32x2 %0, %1, %2, %0;" : "+l"(d) : "l"(a), "l"(b));
}
__device__ __forceinline__ float2 unpack2(ull p) {
    float2 f; asm("mov.b64 {%0,%1}, %2;" : "=f"(f.x), "=f"(f.y) : "l"(p)); return f;
}
__device__ __forceinline__ float tf32r(float f) {
    uint32_t u;
    asm("cvt.rn.tf32.f32 %0, %1;" : "=r"(u) : "f"(f));
    return __uint_as_float(u);
}

// ---------------- mma.sync (compute_103-safe, sm_80-era PTX) ---------------
__device__ __forceinline__ void mma_bf16(float* d, uint32_t a0, uint32_t a1,
                                         uint32_t a2, uint32_t a3,
                                         uint32_t b0, uint32_t b1) {
    asm volatile(
        "mma.sync.aligned.m16n8k16.row.col.f32.bf16.bf16.f32 "
        "{%0,%1,%2,%3}, {%4,%5,%6,%7}, {%8,%9}, {%0,%1,%2,%3};"
        : "+f"(d[0]), "+f"(d[1]), "+f"(d[2]), "+f"(d[3])
        : "r"(a0), "r"(a1), "r"(a2), "r"(a3), "r"(b0), "r"(b1));
}
__device__ __forceinline__ void mma_tf32(float* d, float4 a, uint32_t b0, uint32_t b1) {
    asm volatile(
        "mma.sync.aligned.m16n8k8.row.col.f32.tf32.tf32.f32 "
        "{%0,%1,%2,%3}, {%4,%5,%6,%7}, {%8,%9}, {%0,%1,%2,%3};"
        : "+f"(d[0]), "+f"(d[1]), "+f"(d[2]), "+f"(d[3])
        : "r"(__float_as_uint(a.x)), "r"(__float_as_uint(a.y)),
          "r"(__float_as_uint(a.z)), "r"(__float_as_uint(a.w)),
          "r"(b0), "r"(b1));
}

// ---------------- kernel 0: prep ----------------
__global__ void prep_kernel(const float* __restrict__ weights, const float* __restrict__ A,
                            const float* __restrict__ Wa, const float* __restrict__ ba,
                            const float* __restrict__ Wb, const float* __restrict__ bb,
                            const float* __restrict__ WT1, const float* __restrict__ bT1,
                            const float* __restrict__ WT2, const float* __restrict__ bT2,
                            const float* __restrict__ WST11, const float* __restrict__ bST11,
                            const float* __restrict__ WST12, const float* __restrict__ bST12,
                            const float* __restrict__ Wd, const float* __restrict__ bd,
                            const float* __restrict__ gamma, const float* __restrict__ beta,
                            const float* __restrict__ mean, const float* __restrict__ var) {
    __shared__ float sA[625], sA4[625];
    const int tid = threadIdx.x;
    if (tid < 625) {
        float a = A[tid];
        sA[tid] = a;
        int v = tid / 25, w = tid % 25;
        float a2 = a * a;  // elementwise Chebyshev (torch.pow semantics)
        sA4[tid] = 8.f * a2 * a2 - 8.f * a2 + (v == w ? 1.f : 0.f);
    }
    __syncthreads();
    if (tid < 25) {
        const int w = tid;
        float w0 = weights[0], w1 = weights[1];
        float m = -1e30f;
        for (int v = 0; v < 25; ++v) m = fmaxf(m, sA4[v*25+w] * 0.04f);
        float ssum = 0.f;
        for (int v = 0; v < 25; ++v) ssum += expf(sA4[v*25+w] * 0.04f - m);
        float inv = 1.f / ssum;
        for (int v = 0; v < 25; ++v)
            g_Acomb[v*25+w] = w0 * sA[v*25+w] + w1 * expf(sA4[v*25+w] * 0.04f - m) * inv;
    }
    for (int idx = tid; idx < 9 * 128 * 64; idx += blockDim.x) {
        int tap = idx / 8192, r = idx % 8192;
        int m = r / 64, c = r % 64;
        int g = m >> 4;
        int i = c_i9[g], s = c_s9[g];
        const float* W = (s == 0) ? WT1 : (s == 1) ? WT2 : (s == 2) ? WST11 : WST12;
        g_W9b[idx] = __float2bfloat16(W[((i*16 + (m & 15))*64 + c)*9 + tap]);
    }
    for (int idx = tid; idx < 128; idx += blockDim.x) {
        int g = idx >> 4, c = idx & 15;
        int i = c_i9[g], s = c_s9[g];
        const float* B = (s == 0) ? bT1 : (s == 1) ? bT2 : (s == 2) ? bST11 : bST12;
        g_b9[idx] = B[i*16 + c];
    }
    for (int idx = tid; idx < 160 * 64; idx += blockDim.x) {
        int m = idx / 64, c = idx % 64;
        int g = m >> 4;
        int i = c_i1[g], s = c_s1[g];
        float val;
        if (s == 0)      val = Wa[(i*16 + (m & 15))*64 + c];
        else if (s == 1) val = Wb[(i*16 + (m & 15))*64 + c];
        else if (s == 2) val = WST11[((i*16 + (m & 15))*64 + c)*9 + 4];
        else             val = WST12[((i*16 + (m & 15))*64 + c)*9 + 4];
        g_W1b[idx] = __float2bfloat16(val);
    }
    for (int idx = tid; idx < 160; idx += blockDim.x) {
        int g = idx >> 4, c = idx & 15;
        int i = c_i1[g], s = c_s1[g];
        const float* B = (s == 0) ? ba : (s == 1) ? bb : (s == 2) ? bST11 : bST12;
        g_b1[idx] = B[i*16 + c];
    }
    // Pre-packed tf32 hi/lo A-fragments of (BN-folded Wd)^T for m16n8k8:
    // A[m=o][k], a0:(row,col) a1:(row+8,col) a2:(row,col+4) a3:(row+8,col+4)
    for (int idx = tid; idx < 12288; idx += blockDim.x) {
        int s = idx / 3072, r = idx % 3072;
        int kt = r / 128, r2 = r % 128;
        int lane = r2 >> 2, j = r2 & 3;
        int row = (lane >> 2) + ((j & 1) ? 8 : 0);
        int col = (lane & 3) + ((j & 2) ? 4 : 0);
        int o = 16 * s + row, k = 8 * kt + col;
        int i = k >> 6, c = k & 63;
        float sc = gamma[o] * rsqrtf(var[o] + 1e-5f);
        float w = Wd[(i * 64 + o) * 64 + c] * sc;
        float wh = tf32r(w);
        g_AfH[idx] = wh;
        g_AfL[idx] = tf32r(w - wh);
    }
    for (int o = tid; o < 64; o += blockDim.x) {
        float sc = gamma[o] * rsqrtf(var[o] + 1e-5f);
        g_bd2[o] = (bd[o] + bd[64 + o] + bd[128 + o] - mean[o]) * sc + beta[o];
    }
}

// ---------------- kernel 1: unified conv (mma.sync bf16) + fused gram ------
#define XS_N_STRIDE 72
#define XS_BF16     (512 * XS_N_STRIDE)
#define FT_BF16     (18 * 25 * 132)
#define SMEM_CONV   ((XS_BF16 + FT_BF16) * 2)

__global__ void __launch_bounds__(512, 1) convm_kernel(const float* __restrict__ x) {
    extern __shared__ __nv_bfloat16 smb[];
    __nv_bfloat16* xs = smb;
    __nv_bfloat16* fT = smb + XS_BF16;
    const int n = blockIdx.y, t0 = blockIdx.x * 8;
    const int tid = threadIdx.x, warp = tid >> 5, lane = tid & 31;

    {
        uint32_t* xz = (uint32_t*)xs;
        for (int i = tid; i < XS_BF16 / 2; i += 512) xz[i] = 0u;
    }
    __syncthreads();
    {
        const float* xn = x + (size_t)n * (CC * TT * VV);
        for (int idx = tid; idx < 64 * 16 * 25; idx += 512) {
            int cin = idx / 400, r = idx % 400;
            int tsl = r / 25, v = r % 25;
            int t = t0 - 4 + tsl;
            if (t < 0 || t >= TT) continue;
            xs[(tsl * 32 + v) * XS_N_STRIDE + cin] =
                __float2bfloat16(xn[(cin * TT + t) * VV + v]);
        }
    }
    __syncthreads();

    const int row = lane >> 2;
    const int kq  = (lane & 3) * 2;
    float acc[16][4];

    for (int job = 0; job < 3; ++job) {
        if (job == 2 && warp >= 4) break;
        const int strip = (job == 0) ? (warp >> 1) : (job == 1) ? 8 + (warp >> 1)
                                                                : 16 + (warp >> 1);
        const int half = warp & 1;
        const int is9 = (job == 0);
#pragma unroll
        for (int a = 0; a < 16; ++a)
#pragma unroll
            for (int b = 0; b < 4; ++b) acc[a][b] = 0.f;

        const int ntaps = is9 ? 9 : 1;
        for (int jt = 0; jt < ntaps; ++jt) {
            const int tap = is9 ? jt : 4;
            const __nv_bfloat16* Ab = is9 ? g_W9b + (size_t)(tap * 128 + strip * 16) * 64
                                          : g_W1b + (size_t)(strip - 8) * 16 * 64;
            const __nv_bfloat16* xb = xs + (size_t)(tap * 32 + half * 128 + row) * XS_N_STRIDE;
#pragma unroll
            for (int k0 = 0; k0 < 64; k0 += 16) {
                uint32_t a0 = *(const uint32_t*)(Ab + row * 64 + k0 + kq);
                uint32_t a1 = *(const uint32_t*)(Ab + (row + 8) * 64 + k0 + kq);
                uint32_t a2 = *(const uint32_t*)(Ab + row * 64 + k0 + kq + 8);
                uint32_t a3 = *(const uint32_t*)(Ab + (row + 8) * 64 + k0 + kq + 8);
#pragma unroll
                for (int nt = 0; nt < 16; ++nt) {
                    uint32_t b0 = *(const uint32_t*)(xb + nt * 8 * XS_N_STRIDE + k0 + kq);
                    uint32_t b1 = *(const uint32_t*)(xb + nt * 8 * XS_N_STRIDE + k0 + kq + 8);
                    mma_bf16(acc[nt], a0, a1, a2, a3, b0, b1);
                }
            }
        }
        const float* bias_arr = is9 ? g_b9 + strip * 16 : g_b1 + (strip - 8) * 16;
        const float bias_lo = bias_arr[row];
        const float bias_hi = bias_arr[row + 8];
#pragma unroll
        for (int nt = 0; nt < 16; ++nt)
#pragma unroll
            for (int j = 0; j < 4; ++j) {
                const int ch = row + ((j >= 2) ? 8 : 0);
                const int nl = half * 128 + nt * 8 + (lane & 3) * 2 + (j & 1);
                const int tt = nl >> 5, v = nl & 31;
                if (v < 25)
                    fT[(strip * 25 + v) * 132 + ch * 8 + tt] =
                        __float2bfloat16(acc[nt][j] + ((j >= 2) ? bias_hi : bias_lo));
            }
    }
    __syncthreads();

    if (tid < 450) {
        const int pair = tid / 50, rem = tid % 50;
        const int kh = rem / 25, cell = rem % 25;
        const int v0 = (cell / 5) * 5, w0 = (cell % 5) * 5;
        int br1, gi, gj;
        if (pair < 4) { br1 = 2 * pair;           gi = c_gi9[pair];      gj = c_gj9[pair]; }
        else          { br1 = 8 + 2 * (pair - 4); gi = c_gi1[pair - 4];  gj = c_gj1[pair - 4]; }
        const __nv_bfloat16* f1 = fT + (size_t)(br1 * 25 + v0) * 132 + kh * 64;
        const __nv_bfloat16* f2 = fT + (size_t)((br1 + 1) * 25 + w0) * 132 + kh * 64;
        ull g[5][5];
#pragma unroll
        for (int r = 0; r < 5; ++r)
#pragma unroll
            for (int s = 0; s < 5; ++s) g[r][s] = 0ULL;
        for (int kp = 0; kp < 32; ++kp) {
            ull a[5], b[5];
#pragma unroll
            for (int r = 0; r < 5; ++r) {
                float2 fa = __bfloat1622float2(*(const __nv_bfloat162*)(f1 + r * 132 + kp * 2));
                a[r] = pack2(fa.x, fa.y);
            }
#pragma unroll
            for (int s = 0; s < 5; ++s) {
                float2 fb = __bfloat1622float2(*(const __nv_bfloat162*)(f2 + s * 132 + kp * 2));
                b[s] = pack2(fb.x, fb.y);
            }
#pragma unroll
            for (int r = 0; r < 5; ++r)
#pragma unroll
                for (int s = 0; s < 5; ++s) fma2(g[r][s], a[r], b[s]);
        }
        float* dst = g_Gram + ((size_t)(n * 3 + gi) * 3 + gj) * 625;
#pragma unroll
        for (int r = 0; r < 5; ++r)
#pragma unroll
            for (int s = 0; s < 5; ++s) {
                float2 f = unpack2(g[r][s]);
                atomicAdd(&dst[(v0 + r) * 25 + (w0 + s)], f.x + f.y);
            }
    }
}

// ---------------- kernel 2: softmax + combine into A1 ----------------------
__global__ void smx_kernel(const float* __restrict__ weights) {
    const int n = blockIdx.x, i = blockIdx.y, w = threadIdx.x;
    if (w >= 25) return;
    const float INV = 1.f / 4096.f;
    const float wj[3] = {weights[5], weights[6], weights[7]};
    float a1[25];
#pragma unroll
    for (int v = 0; v < 25; ++v) a1[v] = g_Acomb[v * 25 + w];
    for (int j = 0; j < 3; ++j) {
        const float* gb = g_Gram + ((size_t)(n * 3 + i) * 3 + j) * 625 + w;
        float m = -1e30f;
        for (int v = 0; v < 25; ++v) m = fmaxf(m, gb[v * 25] * INV);
        float s = 0.f;
        for (int v = 0; v < 25; ++v) s += expf(gb[v * 25] * INV - m);
        float inv = wj[j] / s;
        for (int v = 0; v < 25; ++v) a1[v] += inv * expf(gb[v * 25] * INV - m);
    }
    float* out = g_A1 + (size_t)(n * 3 + i) * 625 + w;
    for (int v = 0; v < 25; ++v) out[v * 25] = a1[v];
}

// ---------------- kernel 3: final via tf32 mma ------------------------------
// grid (T/4, N), 256 thr = 8 warps.
// smem floats: zs[192][136] @0 (26112) | AfH @26112 (12288) | AfL @38400 (12288)
//              xs @50688 (1600) | A1s @52288 (1950)   total 54238 f = 216952 B
#define FIN_ZS    0
#define FIN_AFH   26112
#define FIN_AFL   38400
#define FIN_XS    50688
#define FIN_A1    52288
#define SMEM_FIN  216960

__global__ void __launch_bounds__(256, 1) final_kernel(const float* __restrict__ x,
                                                       float* __restrict__ out) {
    extern __shared__ float sm[];
    float* zs  = sm + FIN_ZS;
    float4* AH4 = (float4*)(sm + FIN_AFH);
    float4* AL4 = (float4*)(sm + FIN_AFL);
    float* xs  = sm + FIN_XS;
    float* A1s = sm + FIN_A1;
    const int tb = blockIdx.x, nb = blockIdx.y, tid = threadIdx.x;
    const int warp = tid >> 5, lane = tid & 31;

    {
        const float4* s1 = (const float4*)g_AfH;
        const float4* s2 = (const float4*)g_AfL;
        for (int i = tid; i < 3072; i += 256) { AH4[i] = s1[i]; AL4[i] = s2[i]; }
    }
    for (int idx = tid; idx < 1950; idx += 256) {
        int row = idx / 26, w = idx % 26;
        A1s[idx] = (w < 25) ? g_A1[(size_t)nb * 1875 + row * 25 + w] : 0.f;
    }
    for (int idx = tid; idx < 26112; idx += 256) zs[idx] = 0.f;
    __syncthreads();

    // stage B: z[k=(i,c)][n=t*32+v] fp32-exact, tf32-rounded into zs
    for (int t = 0; t < 4; ++t) {
        const int tg = tb * 4 + t;
        for (int idx = tid; idx < 1600; idx += 256) {
            int c = idx / 25, v = idx % 25;
            xs[idx] = x[((size_t)(nb * 64 + c)) * 6400 + tg * 25 + v];
        }
        __syncthreads();
        for (int idx = tid; idx < 2496; idx += 256) {
            int k = idx / 13, wp = idx % 13, i = k >> 6, c = k & 63;
            ull a = 0ULL;
            const float* xr = &xs[c * 25];
            const float* ar = &A1s[i * 650 + 2 * wp];
#pragma unroll
            for (int u = 0; u < 25; ++u) {
                float xv = xr[u];
                fma2(a, pack2(xv, xv), *(const ull*)&ar[u * 26]);
            }
            float2 f = unpack2(a);
            zs[k * 136 + t * 32 + 2 * wp]     = tf32r(f.x);
            zs[k * 136 + t * 32 + 2 * wp + 1] = tf32r(f.y);
        }
        __syncthreads();
    }

    // stage C: D[64 o][128 n] = (Wh+Wl) @ z via m16n8k8 tf32
    const int s = warp >> 1, h = warp & 1;
    float acc[8][4];
#pragma unroll
    for (int a = 0; a < 8; ++a)
#pragma unroll
        for (int b = 0; b < 4; ++b) acc[a][b] = 0.f;
    const uint32_t* zsu = (const uint32_t*)zs;
    const int bcol = 64 * h + (lane >> 2);
    for (int kt = 0; kt < 24; ++kt) {
        float4 ah = AH4[(s * 24 + kt) * 32 + lane];
        float4 al = AL4[(s * 24 + kt) * 32 + lane];
        const uint32_t* zb0 = zsu + (8 * kt + (lane & 3)) * 136 + bcol;
        const uint32_t* zb1 = zb0 + 4 * 136;
#pragma unroll
        for (int nt = 0; nt < 8; ++nt) {
            uint32_t b0 = zb0[8 * nt], b1 = zb1[8 * nt];
            mma_tf32(acc[nt], ah, b0, b1);
            mma_tf32(acc[nt], al, b0, b1);
        }
    }
    // epilogue: bias + residual + relu
#pragma unroll
    for (int nt = 0; nt < 8; ++nt)
#pragma unroll
        for (int j = 0; j < 4; ++j) {
            int o = 16 * s + (lane >> 2) + ((j & 2) ? 8 : 0);
            int n = 64 * h + 8 * nt + 2 * (lane & 3) + (j & 1);
            int tl = n >> 5, v = n & 31;
            if (v < 25) {
                size_t gi = ((size_t)(nb * 64 + o)) * 6400 + (tb * 4 + tl) * 25 + v;
                out[gi] = fmaxf(acc[nt][j] + g_bd2[o] + x[gi], 0.f);
            }
        }
}

// ---------------- launch ----------------------------------------------------
extern "C" void kernel_launch(void* const* d_in, const int* in_sizes, int n_in,
                              void* d_out, int out_size) {
    const float* x       = (const float*)d_in[0];
    const float* weights = (const float*)d_in[1];
    const float* A       = (const float*)d_in[2];
    const float* Wa      = (const float*)d_in[3];
    const float* ba      = (const float*)d_in[4];
    const float* Wb      = (const float*)d_in[5];
    const float* bb      = (const float*)d_in[6];
    const float* Wd      = (const float*)d_in[7];
    const float* bd      = (const float*)d_in[8];
    const float* WT1     = (const float*)d_in[9];
    const float* bT1     = (const float*)d_in[10];
    const float* WT2     = (const float*)d_in[11];
    const float* bT2     = (const float*)d_in[12];
    const float* WST11   = (const float*)d_in[13];
    const float* bST11   = (const float*)d_in[14];
    const float* WST12   = (const float*)d_in[15];
    const float* bST12   = (const float*)d_in[16];
    const float* bn_g    = (const float*)d_in[17];
    const float* bn_b    = (const float*)d_in[18];
    const float* bn_m    = (const float*)d_in[19];
    const float* bn_v    = (const float*)d_in[20];
    float* out = (float*)d_out;

    cudaFuncSetAttribute(convm_kernel, cudaFuncAttributeMaxDynamicSharedMemorySize, SMEM_CONV);
    cudaFuncSetAttribute(final_kernel, cudaFuncAttributeMaxDynamicSharedMemorySize, SMEM_FIN);

    void* gram_ptr = nullptr;
    cudaGetSymbolAddress(&gram_ptr, g_Gram);

    prep_kernel<<<1, 640>>>(weights, A, Wa, ba, Wb, bb, WT1, bT1, WT2, bT2,
                            WST11, bST11, WST12, bST12, Wd, bd, bn_g, bn_b, bn_m, bn_v);
    cudaMemsetAsync(gram_ptr, 0, sizeof(float) * 64 * 9 * 625);
    convm_kernel<<<dim3(32, NB), 512, SMEM_CONV>>>(x);
    smx_kernel<<<dim3(NB, 3), 32>>>(weights);
    final_kernel<<<dim3(TT / 4, NB), 256, SMEM_FIN>>>(x, out);
}

// round 10
// speedup vs baseline: 1.3037x; 1.3037x over previous
#include <cuda_runtime.h>
#include <cuda_bf16.h>
#include <cstdint>

#define NB   64
#define CC   64
#define TT   256
#define VV   25

typedef unsigned long long ull;

// ---------------- scratch (static device memory) ----------------
__device__ __align__(16) __nv_bfloat16 g_W9b[9 * 128 * 64];  // [tap][ch][cin]
__device__ __align__(16) __nv_bfloat16 g_W1b[160 * 64];      // [ch][cin]
__device__ float g_b9[128];
__device__ float g_b1[160];
__device__ float g_Acomb[625];
__device__ float g_Gram[64 * 9 * 625];
__device__ float g_A1[64 * 3 * 625];
// tf32 hi/lo A-fragments of WdS^stacked [192 x 64]: [12 strip][8 kt][32 lane][4]
__device__ __align__(16) float g_AfH[12288];
__device__ __align__(16) float g_AfL[12288];
__device__ float g_bd2[64];

// branch tables
__constant__ int c_i9[8]  = {0,0,1,1,1,1,2,2};
__constant__ int c_s9[8]  = {0,1,0,1,2,3,0,1};
__constant__ int c_i1[10] = {0,0,0,0,1,1,2,2,2,2};
__constant__ int c_s1[10] = {0,1,2,3,0,1,0,1,2,3};
__constant__ int c_gi9[4] = {0,1,1,2};
__constant__ int c_gj9[4] = {1,1,2,1};
__constant__ int c_gi1[5] = {0,0,1,2,2};
__constant__ int c_gj1[5] = {0,2,0,0,2};

// ---------------- f32x2 helpers ----------------
__device__ __forceinline__ ull pack2(float lo, float hi) {
    ull r; asm("mov.b64 %0, {%1,%2};" : "=l"(r) : "f"(lo), "f"(hi)); return r;
}
__device__ __forceinline__ void fma2(ull& d, ull a, ull b) {
    asm("fma.rn.f32x2 %0, %1, %2, %0;" : "+l"(d) : "l"(a), "l"(b));
}
__device__ __forceinline__ float2 unpack2(ull p) {
    float2 f; asm("mov.b64 {%0,%1}, %2;" : "=f"(f.x), "=f"(f.y) : "l"(p)); return f;
}
__device__ __forceinline__ float tf32r(float f) {
    uint32_t u;
    asm("cvt.rn.tf32.f32 %0, %1;" : "=r"(u) : "f"(f));
    return __uint_as_float(u);
}

// ---------------- mma.sync (compute_103-safe, sm_80-era PTX) ---------------
__device__ __forceinline__ void mma_bf16(float* d, uint32_t a0, uint32_t a1,
                                         uint32_t a2, uint32_t a3,
                                         uint32_t b0, uint32_t b1) {
    asm volatile(
        "mma.sync.aligned.m16n8k16.row.col.f32.bf16.bf16.f32 "
        "{%0,%1,%2,%3}, {%4,%5,%6,%7}, {%8,%9}, {%0,%1,%2,%3};"
        : "+f"(d[0]), "+f"(d[1]), "+f"(d[2]), "+f"(d[3])
        : "r"(a0), "r"(a1), "r"(a2), "r"(a3), "r"(b0), "r"(b1));
}
__device__ __forceinline__ void mma_tf32(float* d, float4 a, uint32_t b0, uint32_t b1) {
    asm volatile(
        "mma.sync.aligned.m16n8k8.row.col.f32.tf32.tf32.f32 "
        "{%0,%1,%2,%3}, {%4,%5,%6,%7}, {%8,%9}, {%0,%1,%2,%3};"
        : "+f"(d[0]), "+f"(d[1]), "+f"(d[2]), "+f"(d[3])
        : "r"(__float_as_uint(a.x)), "r"(__float_as_uint(a.y)),
          "r"(__float_as_uint(a.z)), "r"(__float_as_uint(a.w)),
          "r"(b0), "r"(b1));
}

// ---------------- kernel 0: prep ----------------
__global__ void prep_kernel(const float* __restrict__ weights, const float* __restrict__ A,
                            const float* __restrict__ Wa, const float* __restrict__ ba,
                            const float* __restrict__ Wb, const float* __restrict__ bb,
                            const float* __restrict__ WT1, const float* __restrict__ bT1,
                            const float* __restrict__ WT2, const float* __restrict__ bT2,
                            const float* __restrict__ WST11, const float* __restrict__ bST11,
                            const float* __restrict__ WST12, const float* __restrict__ bST12,
                            const float* __restrict__ Wd, const float* __restrict__ bd,
                            const float* __restrict__ gamma, const float* __restrict__ beta,
                            const float* __restrict__ mean, const float* __restrict__ var) {
    __shared__ float sA[625], sA4[625];
    const int tid = threadIdx.x;
    if (tid < 625) {
        float a = A[tid];
        sA[tid] = a;
        int v = tid / 25, w = tid % 25;
        float a2 = a * a;  // elementwise Chebyshev (torch.pow semantics)
        sA4[tid] = 8.f * a2 * a2 - 8.f * a2 + (v == w ? 1.f : 0.f);
    }
    __syncthreads();
    if (tid < 25) {
        const int w = tid;
        float w0 = weights[0], w1 = weights[1];
        float m = -1e30f;
        for (int v = 0; v < 25; ++v) m = fmaxf(m, sA4[v*25+w] * 0.04f);
        float ssum = 0.f;
        for (int v = 0; v < 25; ++v) ssum += expf(sA4[v*25+w] * 0.04f - m);
        float inv = 1.f / ssum;
        for (int v = 0; v < 25; ++v)
            g_Acomb[v*25+w] = w0 * sA[v*25+w] + w1 * expf(sA4[v*25+w] * 0.04f - m) * inv;
    }
    for (int idx = tid; idx < 9 * 128 * 64; idx += blockDim.x) {
        int tap = idx / 8192, r = idx % 8192;
        int m = r / 64, c = r % 64;
        int g = m >> 4;
        int i = c_i9[g], s = c_s9[g];
        const float* W = (s == 0) ? WT1 : (s == 1) ? WT2 : (s == 2) ? WST11 : WST12;
        g_W9b[idx] = __float2bfloat16(W[((i*16 + (m & 15))*64 + c)*9 + tap]);
    }
    for (int idx = tid; idx < 128; idx += blockDim.x) {
        int g = idx >> 4, c = idx & 15;
        int i = c_i9[g], s = c_s9[g];
        const float* B = (s == 0) ? bT1 : (s == 1) ? bT2 : (s == 2) ? bST11 : bST12;
        g_b9[idx] = B[i*16 + c];
    }
    for (int idx = tid; idx < 160 * 64; idx += blockDim.x) {
        int m = idx / 64, c = idx % 64;
        int g = m >> 4;
        int i = c_i1[g], s = c_s1[g];
        float val;
        if (s == 0)      val = Wa[(i*16 + (m & 15))*64 + c];
        else if (s == 1) val = Wb[(i*16 + (m & 15))*64 + c];
        else if (s == 2) val = WST11[((i*16 + (m & 15))*64 + c)*9 + 4];
        else             val = WST12[((i*16 + (m & 15))*64 + c)*9 + 4];
        g_W1b[idx] = __float2bfloat16(val);
    }
    for (int idx = tid; idx < 160; idx += blockDim.x) {
        int g = idx >> 4, c = idx & 15;
        int i = c_i1[g], s = c_s1[g];
        const float* B = (s == 0) ? ba : (s == 1) ? bb : (s == 2) ? bST11 : bST12;
        g_b1[idx] = B[i*16 + c];
    }
    // tf32 hi/lo A-fragments for U = WdS @ x (m16n8k8):
    // A-frag: j&1 -> row+8, j&2 -> col+4  (verified in R7 silicon)
    for (int idx = tid; idx < 12288; idx += blockDim.x) {
        int j = idx & 3, lane = (idx >> 2) & 31, kt = (idx >> 7) & 7, s = idx >> 10;
        int row = (lane >> 2) + ((j & 1) ? 8 : 0);
        int col = (lane & 3) + ((j & 2) ? 4 : 0);
        int m = 16 * s + row, c = 8 * kt + col;
        int i = m >> 6, o = m & 63;
        float sc = gamma[o] * rsqrtf(var[o] + 1e-5f);
        float w = Wd[(i * 64 + o) * 64 + c] * sc;
        float wh = tf32r(w);
        g_AfH[idx] = wh;
        g_AfL[idx] = tf32r(w - wh);
    }
    for (int o = tid; o < 64; o += blockDim.x) {
        float sc = gamma[o] * rsqrtf(var[o] + 1e-5f);
        g_bd2[o] = (bd[o] + bd[64 + o] + bd[128 + o] - mean[o]) * sc + beta[o];
    }
}

// ---------------- kernel 1: unified conv (mma.sync bf16) + fused gram ------
#define XS_N_STRIDE 72
#define XS_BF16     (512 * XS_N_STRIDE)
#define FT_BF16     (18 * 25 * 132)
#define SMEM_CONV   ((XS_BF16 + FT_BF16) * 2)

__global__ void __launch_bounds__(512, 1) convm_kernel(const float* __restrict__ x) {
    extern __shared__ __nv_bfloat16 smb[];
    __nv_bfloat16* xs = smb;
    __nv_bfloat16* fT = smb + XS_BF16;
    const int n = blockIdx.y, t0 = blockIdx.x * 8;
    const int tid = threadIdx.x, warp = tid >> 5, lane = tid & 31;

    {
        uint32_t* xz = (uint32_t*)xs;
        for (int i = tid; i < XS_BF16 / 2; i += 512) xz[i] = 0u;
    }
    __syncthreads();
    {
        const float* xn = x + (size_t)n * (CC * TT * VV);
        for (int idx = tid; idx < 64 * 16 * 25; idx += 512) {
            int cin = idx / 400, r = idx % 400;
            int tsl = r / 25, v = r % 25;
            int t = t0 - 4 + tsl;
            if (t < 0 || t >= TT) continue;
            xs[(tsl * 32 + v) * XS_N_STRIDE + cin] =
                __float2bfloat16(xn[(cin * TT + t) * VV + v]);
        }
    }
    __syncthreads();

    const int row = lane >> 2;
    const int kq  = (lane & 3) * 2;
    float acc[16][4];

    for (int job = 0; job < 3; ++job) {
        if (job == 2 && warp >= 4) break;
        const int strip = (job == 0) ? (warp >> 1) : (job == 1) ? 8 + (warp >> 1)
                                                                : 16 + (warp >> 1);
        const int half = warp & 1;
        const int is9 = (job == 0);
#pragma unroll
        for (int a = 0; a < 16; ++a)
#pragma unroll
            for (int b = 0; b < 4; ++b) acc[a][b] = 0.f;

        const int ntaps = is9 ? 9 : 1;
        for (int jt = 0; jt < ntaps; ++jt) {
            const int tap = is9 ? jt : 4;
            const __nv_bfloat16* Ab = is9 ? g_W9b + (size_t)(tap * 128 + strip * 16) * 64
                                          : g_W1b + (size_t)(strip - 8) * 16 * 64;
            const __nv_bfloat16* xb = xs + (size_t)(tap * 32 + half * 128 + row) * XS_N_STRIDE;
#pragma unroll
            for (int k0 = 0; k0 < 64; k0 += 16) {
                uint32_t a0 = *(const uint32_t*)(Ab + row * 64 + k0 + kq);
                uint32_t a1 = *(const uint32_t*)(Ab + (row + 8) * 64 + k0 + kq);
                uint32_t a2 = *(const uint32_t*)(Ab + row * 64 + k0 + kq + 8);
                uint32_t a3 = *(const uint32_t*)(Ab + (row + 8) * 64 + k0 + kq + 8);
#pragma unroll
                for (int nt = 0; nt < 16; ++nt) {
                    uint32_t b0 = *(const uint32_t*)(xb + nt * 8 * XS_N_STRIDE + k0 + kq);
                    uint32_t b1 = *(const uint32_t*)(xb + nt * 8 * XS_N_STRIDE + k0 + kq + 8);
                    mma_bf16(acc[nt], a0, a1, a2, a3, b0, b1);
                }
            }
        }
        const float* bias_arr = is9 ? g_b9 + strip * 16 : g_b1 + (strip - 8) * 16;
        const float bias_lo = bias_arr[row];
        const float bias_hi = bias_arr[row + 8];
#pragma unroll
        for (int nt = 0; nt < 16; ++nt)
#pragma unroll
            for (int j = 0; j < 4; ++j) {
                const int ch = row + ((j >= 2) ? 8 : 0);
                const int nl = half * 128 + nt * 8 + (lane & 3) * 2 + (j & 1);
                const int tt = nl >> 5, v = nl & 31;
                if (v < 25)
                    fT[(strip * 25 + v) * 132 + ch * 8 + tt] =
                        __float2bfloat16(acc[nt][j] + ((j >= 2) ? bias_hi : bias_lo));
            }
    }
    __syncthreads();

    if (tid < 450) {
        const int pair = tid / 50, rem = tid % 50;
        const int kh = rem / 25, cell = rem % 25;
        const int v0 = (cell / 5) * 5, w0 = (cell % 5) * 5;
        int br1, gi, gj;
        if (pair < 4) { br1 = 2 * pair;           gi = c_gi9[pair];      gj = c_gj9[pair]; }
        else          { br1 = 8 + 2 * (pair - 4); gi = c_gi1[pair - 4];  gj = c_gj1[pair - 4]; }
        const __nv_bfloat16* f1 = fT + (size_t)(br1 * 25 + v0) * 132 + kh * 64;
        const __nv_bfloat16* f2 = fT + (size_t)((br1 + 1) * 25 + w0) * 132 + kh * 64;
        ull g[5][5];
#pragma unroll
        for (int r = 0; r < 5; ++r)
#pragma unroll
            for (int s = 0; s < 5; ++s) g[r][s] = 0ULL;
        for (int kp = 0; kp < 32; ++kp) {
            ull a[5], b[5];
#pragma unroll
            for (int r = 0; r < 5; ++r) {
                float2 fa = __bfloat1622float2(*(const __nv_bfloat162*)(f1 + r * 132 + kp * 2));
                a[r] = pack2(fa.x, fa.y);
            }
#pragma unroll
            for (int s = 0; s < 5; ++s) {
                float2 fb = __bfloat1622float2(*(const __nv_bfloat162*)(f2 + s * 132 + kp * 2));
                b[s] = pack2(fb.x, fb.y);
            }
#pragma unroll
            for (int r = 0; r < 5; ++r)
#pragma unroll
                for (int s = 0; s < 5; ++s) fma2(g[r][s], a[r], b[s]);
        }
        float* dst = g_Gram + ((size_t)(n * 3 + gi) * 3 + gj) * 625;
#pragma unroll
        for (int r = 0; r < 5; ++r)
#pragma unroll
            for (int s = 0; s < 5; ++s) {
                float2 f = unpack2(g[r][s]);
                atomicAdd(&dst[(v0 + r) * 25 + (w0 + s)], f.x + f.y);
            }
    }
}

// ---------------- kernel 2: softmax + combine into A1 ----------------------
__global__ void smx_kernel(const float* __restrict__ weights) {
    const int n = blockIdx.x, i = blockIdx.y, w = threadIdx.x;
    if (w >= 25) return;
    const float INV = 1.f / 4096.f;
    const float wj[3] = {weights[5], weights[6], weights[7]};
    float a1[25];
#pragma unroll
    for (int v = 0; v < 25; ++v) a1[v] = g_Acomb[v * 25 + w];
    for (int j = 0; j < 3; ++j) {
        const float* gb = g_Gram + ((size_t)(n * 3 + i) * 3 + j) * 625 + w;
        float m = -1e30f;
        for (int v = 0; v < 25; ++v) m = fmaxf(m, gb[v * 25] * INV);
        float s = 0.f;
        for (int v = 0; v < 25; ++v) s += expf(gb[v * 25] * INV - m);
        float inv = wj[j] / s;
        for (int v = 0; v < 25; ++v) a1[v] += inv * expf(gb[v * 25] * INV - m);
    }
    float* out = g_A1 + (size_t)(n * 3 + i) * 625 + w;
    for (int v = 0; v < 25; ++v) out[v * 25] = a1[v];
}

// ---------------- kernel 3: fin2 — U = WdS@x (tf32 mma), out = Σ u_i@A1_i --
// grid (32 tb of 8t, 64 n), 512 thr = 16 warps.
// smem floats: U[192][209] @0 (40128) | xs[64][200] @40128 (12800)
//              A1u (975 ull) @52928 (1950)   total 54878 f = 219512 B
#define F2_U    0
#define F2_XS   40128
#define F2_A1   52928
#define SMEM_F2 219520

__global__ void __launch_bounds__(512, 1) fin2_kernel(const float* __restrict__ x,
                                                      float* __restrict__ out) {
    extern __shared__ float sm[];
    float* U  = sm + F2_U;          // stride 209
    float* xs = sm + F2_XS;         // stride 200 (200%32=8, B-frag bijection)
    ull* A1u  = (ull*)(sm + F2_A1); // [i*25+v][13 wp]
    const int tb = blockIdx.x, nb = blockIdx.y, tid = threadIdx.x;
    const int warp = tid >> 5, lane = tid & 31;

    // stage x (tf32-rounded) — (t*25+v) contiguous in gmem
    for (int idx = tid; idx < 12800; idx += 512) {
        int c = idx / 200, j = idx % 200;
        xs[c * 200 + j] = tf32r(x[((size_t)(nb * 64 + c)) * 6400 + tb * 200 + j]);
    }
    // stage A1 as ull pairs
    for (int idx = tid; idx < 975; idx += 512) {
        int wp = idx % 13, r = idx / 13;   // r = i*25+v
        const float* a = g_A1 + (size_t)nb * 1875 + (r / 25) * 625 + (r % 25) * 25;
        float lo = a[2 * wp];
        float hi = (2 * wp + 1 < 25) ? a[2 * wp + 1] : 0.f;
        A1u[idx] = pack2(lo, hi);
    }
    __syncthreads();

    // G1: U[192][200] = WdS @ xs via m16n8k8 tf32 (hi/lo exact W)
    const uint32_t* xsu = (const uint32_t*)xs;
    const float4* AH4 = (const float4*)g_AfH;
    const float4* AL4 = (const float4*)g_AfL;
    for (int jj = 0; jj < 2; ++jj) {
        if (jj == 1 && warp >= 8) break;
        const int job = jj ? 16 + warp : warp;
        const int s = job >> 1, nh = job & 1;
        const int nt0 = nh * 13, nts = nh ? 12 : 13;
        float acc[13][4];
#pragma unroll
        for (int a = 0; a < 13; ++a)
#pragma unroll
            for (int b = 0; b < 4; ++b) acc[a][b] = 0.f;
#pragma unroll
        for (int kt = 0; kt < 8; ++kt) {
            float4 ah = AH4[(s * 8 + kt) * 32 + lane];
            float4 al = AL4[(s * 8 + kt) * 32 + lane];
            const uint32_t* xb0 = xsu + (8 * kt + (lane & 3)) * 200 + (lane >> 2);
            const uint32_t* xb1 = xb0 + 4 * 200;
            for (int nt = 0; nt < nts; ++nt) {
                uint32_t b0 = xb0[(nt0 + nt) * 8];
                uint32_t b1 = xb1[(nt0 + nt) * 8];
                mma_tf32(acc[nt], ah, b0, b1);
                mma_tf32(acc[nt], al, b0, b1);
            }
        }
        // D-frag store: j&2 -> row+8, j&1 -> col+1  (R7-verified convention)
        for (int nt = 0; nt < nts; ++nt)
#pragma unroll
            for (int j = 0; j < 4; ++j) {
                int r = 16 * s + (lane >> 2) + ((j & 2) ? 8 : 0);
                int col = (nt0 + nt) * 8 + 2 * (lane & 3) + (j & 1);
                U[r * 209 + col] = acc[nt][j];
            }
    }
    __syncthreads();

    // G2: thread = (t, o); out[o][w] = sum_{i,v} U[i*64+o][t*25+v] * A1[i][v][w]
    {
        const int t = tid >> 6, o = tid & 63;
        ull acc[13];
#pragma unroll
        for (int wp = 0; wp < 13; ++wp) acc[wp] = 0ULL;
#pragma unroll
        for (int i = 0; i < 3; ++i) {
            const float* Up = U + (i * 64 + o) * 209 + t * 25;
            const ull* Ap = A1u + i * 325;
#pragma unroll
            for (int v = 0; v < 25; ++v) {
                float u = Up[v];
                ull uu = pack2(u, u);
                const ull* a = Ap + v * 13;
#pragma unroll
                for (int wp = 0; wp < 13; ++wp) fma2(acc[wp], uu, a[wp]);
            }
        }
        const float bias = g_bd2[o];
        const size_t base = ((size_t)(nb * 64 + o)) * 6400 + (size_t)(tb * 8 + t) * 25;
#pragma unroll
        for (int wp = 0; wp < 13; ++wp) {
            float2 f = unpack2(acc[wp]);
            int w = 2 * wp;
            out[base + w] = fmaxf(f.x + bias + x[base + w], 0.f);
            if (w + 1 < 25)
                out[base + w + 1] = fmaxf(f.y + bias + x[base + w + 1], 0.f);
        }
    }
}

// ---------------- launch ----------------------------------------------------
extern "C" void kernel_launch(void* const* d_in, const int* in_sizes, int n_in,
                              void* d_out, int out_size) {
    const float* x       = (const float*)d_in[0];
    const float* weights = (const float*)d_in[1];
    const float* A       = (const float*)d_in[2];
    const float* Wa      = (const float*)d_in[3];
    const float* ba      = (const float*)d_in[4];
    const float* Wb      = (const float*)d_in[5];
    const float* bb      = (const float*)d_in[6];
    const float* Wd      = (const float*)d_in[7];
    const float* bd      = (const float*)d_in[8];
    const float* WT1     = (const float*)d_in[9];
    const float* bT1     = (const float*)d_in[10];
    const float* WT2     = (const float*)d_in[11];
    const float* bT2     = (const float*)d_in[12];
    const float* WST11   = (const float*)d_in[13];
    const float* bST11   = (const float*)d_in[14];
    const float* WST12   = (const float*)d_in[15];
    const float* bST12   = (const float*)d_in[16];
    const float* bn_g    = (const float*)d_in[17];
    const float* bn_b    = (const float*)d_in[18];
    const float* bn_m    = (const float*)d_in[19];
    const float* bn_v    = (const float*)d_in[20];
    float* out = (float*)d_out;

    cudaFuncSetAttribute(convm_kernel, cudaFuncAttributeMaxDynamicSharedMemorySize, SMEM_CONV);
    cudaFuncSetAttribute(fin2_kernel,  cudaFuncAttributeMaxDynamicSharedMemorySize, SMEM_F2);

    void* gram_ptr = nullptr;
    cudaGetSymbolAddress(&gram_ptr, g_Gram);

    prep_kernel<<<1, 640>>>(weights, A, Wa, ba, Wb, bb, WT1, bT1, WT2, bT2,
                            WST11, bST11, WST12, bST12, Wd, bd, bn_g, bn_b, bn_m, bn_v);
    cudaMemsetAsync(gram_ptr, 0, sizeof(float) * 64 * 9 * 625);
    convm_kernel<<<dim3(32, NB), 512, SMEM_CONV>>>(x);
    smx_kernel<<<dim3(NB, 3), 32>>>(weights);
    fin2_kernel<<<dim3(32, NB), 512, SMEM_F2>>>(x, out);
}